// round 11
// baseline (speedup 1.0000x reference)
#include <cuda_runtime.h>
#include <cuda_bf16.h>
#include <cstdint>

// ============================================================================
// LRML scoring, single fused kernel, bf16 m16n8k16 tensor-core GEMM:
//   logits[n,c] = item[n] . W[c]; columns:
//     c in [0,336): b*21+j -> u_b[d]*K[d,j] (j<20); j==20 -> u_b[d]
//     c in [336,356): mem_m[d] (IM);  [356,360) dead pad
//   score^2 = |u|^2 + |item|^2 - 2 u.item + 2 att.(UM - IM) + att^T G att
// R11: CHUNK=64/NSUB=4 (B frags amortized 2x, 3 barriers per 64 items),
//   single 64-row Ls + 1024-pair epilogue, float4 G loads in the Gram form,
//   no softmax max-subtraction (logits tiny), UM/u2/G computed in-kernel.
// W stored in B-fragment order: block(f,p)=256B, lane owns 8B (see R10).
// A row-major bf16 (256B rows), chunk-XOR swizzle phys = c ^ (r&7).
// ============================================================================

#define D_DIM   128
#define M_DIM   20
#define B_USERS 16
#define C_USE   356
#define C_W     360
#define NFRAGS  45
#define CHUNK   64
#define NSUB    4
#define NJ      6
#define LSTRIDE 374
#define GRID    148

// dynamic smem byte offsets
#define WF_BYTES   (48 * 8 * 256)            // 98304
#define AS_OFF     WF_BYTES
#define AS_BYTES   (CHUNK * 256)             // 16384
#define LS_OFF     (AS_OFF + AS_BYTES)       // 114688
#define LS_BYTES   (CHUNK * LSTRIDE * 4)     // 95744
#define SMEM_TOTAL (LS_OFF + LS_BYTES)       // 210432

__device__ __forceinline__ uint32_t smem_u32(const void* p) {
    uint32_t a;
    asm("{ .reg .u64 t; cvta.to.shared.u64 t, %1; cvt.u32.u64 %0, t; }"
        : "=r"(a) : "l"(p));
    return a;
}
// pack two fp32 into bf16x2 (lo = first element)
__device__ __forceinline__ unsigned bf16pack(float lo, float hi) {
    unsigned r;
    asm("cvt.rn.bf16x2.f32 %0, %1, %2;" : "=r"(r) : "f"(hi), "f"(lo));
    return r;
}

__device__ __forceinline__ void mma_bf16(float* c, const unsigned* a,
                                         unsigned b0, unsigned b1) {
    asm volatile(
        "mma.sync.aligned.m16n8k16.row.col.f32.bf16.bf16.f32 "
        "{%0,%1,%2,%3}, {%4,%5,%6,%7}, {%8,%9}, {%0,%1,%2,%3};"
        : "+f"(c[0]), "+f"(c[1]), "+f"(c[2]), "+f"(c[3])
        : "r"(a[0]), "r"(a[1]), "r"(a[2]), "r"(a[3]), "r"(b0), "r"(b1));
}

__device__ __forceinline__ void ldmatrix4(unsigned* r, uint32_t addr) {
    asm volatile("ldmatrix.sync.aligned.m8n8.x4.shared.b16 {%0,%1,%2,%3}, [%4];"
                 : "=r"(r[0]), "=r"(r[1]), "=r"(r[2]), "=r"(r[3]) : "r"(addr));
}
__device__ __forceinline__ void lds64(unsigned& b0, unsigned& b1, uint32_t addr) {
    asm volatile("ld.shared.v2.u32 {%0,%1}, [%2];" : "=r"(b0), "=r"(b1) : "r"(addr));
}
__device__ __forceinline__ void sts128(uint32_t addr, unsigned w0, unsigned w1,
                                       unsigned w2, unsigned w3) {
    asm volatile("st.shared.v4.u32 [%0], {%1,%2,%3,%4};"
                 :: "r"(addr), "r"(w0), "r"(w1), "r"(w2), "r"(w3) : "memory");
}
__device__ __forceinline__ void sts32(uint32_t addr, unsigned w) {
    asm volatile("st.shared.u32 [%0], %1;" :: "r"(addr), "r"(w) : "memory");
}

__device__ __forceinline__ float2 ffma2(float2 a, float2 b, float2 c) {
    unsigned long long ra = *reinterpret_cast<unsigned long long*>(&a);
    unsigned long long rb = *reinterpret_cast<unsigned long long*>(&b);
    unsigned long long rc = *reinterpret_cast<unsigned long long*>(&c);
    unsigned long long rd;
    asm("fma.rn.f32x2 %0, %1, %2, %3;" : "=l"(rd) : "l"(ra), "l"(rb), "l"(rc));
    return *reinterpret_cast<float2*>(&rd);
}

// ids may be int64 or (silently downcast) int32 — sniff layout.
__device__ __forceinline__ void sniff_uids(const void* ids_raw, int* s_uid) {
    const long long* p64 = (const long long*)ids_raw;
    const int*       p32 = (const int*)ids_raw;
    bool is64 = true;
    for (int i = 0; i < 8; i++) {
        long long v = p64[i];
        if (v < 0 || v >= (1LL << 31)) is64 = false;
    }
    for (int i = 0; i < B_USERS; i++)
        s_uid[i] = is64 ? (int)p64[i] : p32[i];
}

// ----------------------------------------------------------------------------
// Single fused kernel: 148 persistent CTAs, 8 warps, 64-item chunks.
// ----------------------------------------------------------------------------
__global__ void __launch_bounds__(256, 1)
fused_kernel(const float* __restrict__ items,
             const float* __restrict__ users,
             const float* __restrict__ keyM,
             const float* __restrict__ mems,
             const void*  __restrict__ ids_raw,
             float* __restrict__ out, int N)
{
    extern __shared__ char smem_c[];
    float* Ls = (float*)(smem_c + LS_OFF);
    const uint32_t sbase = smem_u32(smem_c);
    const uint32_t Wb = sbase;
    const uint32_t Ab = sbase + AS_OFF;

    __shared__ int s_uid[B_USERS];
    __shared__ float Gs[M_DIM * M_DIM];
    __shared__ float UMs[B_USERS * M_DIM];
    __shared__ float u2s[B_USERS];
    __shared__ float it2s[CHUNK];

    const int tid  = threadIdx.x;
    const int warp = tid >> 5;
    const int lane = tid & 31;
    const int g    = lane >> 2;
    const int tig  = lane & 3;
    const int l15  = lane & 15, hi = lane >> 4, l7 = lane & 7;

    if (tid == 0) sniff_uids(ids_raw, s_uid);
    __syncthreads();

    // ---- build W (bf16) directly in B-fragment order ----
    for (int idx = tid; idx < C_W * 64; idx += 256) {
        int c = idx >> 6, kp = idx & 63;
        float w0 = 0.f, w1 = 0.f;
        int k0 = 2 * kp;
        if (c < B_USERS * 21) {
            int b = c / 21, j = c - b * 21;
            float ua = users[(size_t)s_uid[b] * D_DIM + k0];
            float ub = users[(size_t)s_uid[b] * D_DIM + k0 + 1];
            if (j < M_DIM) {
                w0 = ua * keyM[k0 * M_DIM + j];
                w1 = ub * keyM[(k0 + 1) * M_DIM + j];
            } else { w0 = ua; w1 = ub; }
        } else if (c < C_USE) {
            w0 = mems[(c - B_USERS * 21) * D_DIM + k0];
            w1 = mems[(c - B_USERS * 21) * D_DIM + k0 + 1];
        }
        int f = c >> 3, gg = c & 7;
        int p = kp >> 3, tg = kp & 3, half = (kp >> 2) & 1;
        uint32_t addr = Wb + (uint32_t)((f * 8 + p) * 256 + (4 * gg + tg) * 8 + half * 4);
        sts32(addr, bf16pack(w0, w1));
    }

    // ---- in-kernel precompute: UM (320), u2 (16), G (400) dots, warp-per-dot ----
    for (int t = warp; t < 736; t += 8) {
        const float4 *pa, *pb;
        float* dst;
        if (t < 320) {
            int b = t / M_DIM, m = t - b * M_DIM;
            pa = (const float4*)(users + (size_t)s_uid[b] * D_DIM);
            pb = (const float4*)(mems + m * D_DIM);
            dst = &UMs[t];
        } else if (t < 336) {
            int b = t - 320;
            pa = (const float4*)(users + (size_t)s_uid[b] * D_DIM);
            pb = pa;
            dst = &u2s[b];
        } else {
            int x = t - 336;
            pa = (const float4*)(mems + (x / M_DIM) * D_DIM);
            pb = (const float4*)(mems + (x % M_DIM) * D_DIM);
            dst = &Gs[x];
        }
        float4 a = pa[lane], b = pb[lane];
        float s = a.x * b.x + a.y * b.y + a.z * b.z + a.w * b.w;
#pragma unroll
        for (int o = 16; o; o >>= 1) s += __shfl_xor_sync(0xffffffffu, s, o);
        if (lane == 0) *dst = s;
    }

    // per-thread B-frag base addresses
    uint32_t bjb[NJ];
#pragma unroll
    for (int j = 0; j < NJ; j++) {
        int f = warp + 8 * j;
        if (f >= NFRAGS) f = 0;              // harmless duplicate, never dumped
        bjb[j] = Wb + (uint32_t)(f * 2048 + lane * 8);
    }

    const float4* itemsv = (const float4*)items;
    __syncthreads();   // W + precompute visible

    for (int base = blockIdx.x * CHUNK; base < N; base += GRID * CHUNK) {
        // ---- stage A: 512 slots, 2 per thread; it2 partials ----
#pragma unroll
        for (int ps = 0; ps < 2; ps++) {
            int slot = tid + ps * 256;
            int r = slot >> 3, q = slot & 7;
            int n = base + r;
            float4 v0, v1, v2, v3;
            if (n < N) {
                const float4* src = itemsv + (size_t)n * 32;
                v0 = src[2 * q]; v1 = src[2 * q + 1];
                v2 = src[16 + 2 * q]; v3 = src[17 + 2 * q];
            } else {
                v0 = v1 = v2 = v3 = make_float4(0.f, 0.f, 0.f, 0.f);
            }
            float s = v0.x*v0.x + v0.y*v0.y + v0.z*v0.z + v0.w*v0.w
                    + v1.x*v1.x + v1.y*v1.y + v1.z*v1.z + v1.w*v1.w
                    + v2.x*v2.x + v2.y*v2.y + v2.z*v2.z + v2.w*v2.w
                    + v3.x*v3.x + v3.y*v3.y + v3.z*v3.z + v3.w*v3.w;
#pragma unroll
            for (int o = 4; o; o >>= 1)
                s += __shfl_down_sync(0xffffffffu, s, o, 8);
            if (q == 0) it2s[r] = s;

            uint32_t a1 = Ab + (uint32_t)(r * 256 + ((q)     ^ (r & 7)) * 16);
            uint32_t a2 = Ab + (uint32_t)(r * 256 + ((q + 8) ^ (r & 7)) * 16);
            sts128(a1, bf16pack(v0.x, v0.y), bf16pack(v0.z, v0.w),
                       bf16pack(v1.x, v1.y), bf16pack(v1.z, v1.w));
            sts128(a2, bf16pack(v2.x, v2.y), bf16pack(v2.z, v2.w),
                       bf16pack(v3.x, v3.y), bf16pack(v3.z, v3.w));
        }
        __syncthreads();

        // ---- mma mainloop: 8 k16-steps x 4 subtiles x 6 frags ----
        float acc[NSUB][NJ][4];
#pragma unroll
        for (int s = 0; s < NSUB; s++)
#pragma unroll
            for (int j = 0; j < NJ; j++)
#pragma unroll
                for (int q = 0; q < 4; q++) acc[s][j][q] = 0.f;

#pragma unroll
        for (int p = 0; p < 8; p++) {
            const uint32_t phys = (uint32_t)(((2 * p + hi) ^ l7) << 4);
            unsigned A0[4], A1[4], A2[4], A3[4];
            ldmatrix4(A0, Ab + (uint32_t)((0  + l15) * 256) + phys);
            ldmatrix4(A1, Ab + (uint32_t)((16 + l15) * 256) + phys);
            ldmatrix4(A2, Ab + (uint32_t)((32 + l15) * 256) + phys);
            ldmatrix4(A3, Ab + (uint32_t)((48 + l15) * 256) + phys);
#pragma unroll
            for (int j = 0; j < NJ; j++) {
                unsigned b0, b1;
                lds64(b0, b1, bjb[j] + (uint32_t)(p * 256));
                mma_bf16(acc[0][j], A0, b0, b1);
                mma_bf16(acc[1][j], A1, b0, b1);
                mma_bf16(acc[2][j], A2, b0, b1);
                mma_bf16(acc[3][j], A3, b0, b1);
            }
        }
        // Ls free here: previous chunk's epilogue finished before loop-bottom sync

        // ---- dump all 4 subtiles -> Ls[64 rows] ----
#pragma unroll
        for (int s = 0; s < NSUB; s++) {
#pragma unroll
            for (int j = 0; j < NJ; j++) {
                int f = warp + 8 * j;
                if (f < NFRAGS) {
                    int col = f * 8 + 2 * tig;
                    *(float2*)&Ls[(s * 16 + g) * LSTRIDE + col] =
                        make_float2(acc[s][j][0], acc[s][j][1]);
                    *(float2*)&Ls[(s * 16 + g + 8) * LSTRIDE + col] =
                        make_float2(acc[s][j][2], acc[s][j][3]);
                }
            }
        }
        __syncthreads();

        // ---- epilogue: 1024 pairs, 4 per thread ----
#pragma unroll 1
        for (int pass = 0; pass < 4; pass++) {
            const int row = (tid & 15) + 16 * pass;
            const int b   = tid >> 4;
            const int n   = base + row;
            if (n < N) {
                const float* srow = &Ls[row * LSTRIDE];
                const float* lb = srow + b * 21;

                float l[M_DIM];
#pragma unroll
                for (int j = 0; j < M_DIM; j++) l[j] = lb[j];
                const float uit = lb[M_DIM];

                // softmax numerators without max-shift (|logits| << 1)
                float2 e2[M_DIM / 2];
                float S = 0.f;
#pragma unroll
                for (int j = 0; j < M_DIM / 2; j++) {
                    float ea = __expf(l[2 * j]);
                    float eb = __expf(l[2 * j + 1]);
                    e2[j] = make_float2(ea, eb);
                    S += ea + eb;
                }

                // num1 = e . (UM - IM)
                float2 acc1 = make_float2(0.f, 0.f);
#pragma unroll
                for (int j = 0; j < M_DIM / 2; j++) {
                    float2 um = *(const float2*)&UMs[b * M_DIM + 2 * j];
                    float2 im = *(const float2*)&srow[B_USERS * 21 + 2 * j];
                    acc1 = ffma2(e2[j], make_float2(um.x - im.x, um.y - im.y), acc1);
                }
                float num1 = acc1.x + acc1.y;

                // Q = e^T G e, float4 row loads (rows 16B-aligned: stride 80B)
                float Q = 0.f;
#pragma unroll
                for (int m = 0; m < M_DIM; m++) {
                    const float4* Gr = (const float4*)&Gs[m * M_DIM];
                    float2 ga = make_float2(0.f, 0.f);
#pragma unroll
                    for (int j4 = 0; j4 < 5; j4++) {
                        float4 Gv = Gr[j4];
                        ga = ffma2(make_float2(Gv.x, Gv.y), e2[2 * j4], ga);
                        ga = ffma2(make_float2(Gv.z, Gv.w), e2[2 * j4 + 1], ga);
                    }
                    float em = (m & 1) ? e2[m >> 1].y : e2[m >> 1].x;
                    Q = fmaf(em, ga.x + ga.y, Q);
                }

                float invS = 1.f / S;
                float s2 = u2s[b] + it2s[row] - 2.f * uit
                         + 2.f * num1 * invS + Q * invS * invS;
                out[(size_t)b * N + n] = -sqrtf(fmaxf(s2, 0.f));
            }
        }
        __syncthreads();   // Ls/it2s/As consumed before next chunk's writes
    }
}

// ----------------------------------------------------------------------------
extern "C" void kernel_launch(void* const* d_in, const int* in_sizes, int n_in,
                              void* d_out, int out_size)
{
    const float* users = (const float*)d_in[0];
    const float* items = (const float*)d_in[1];
    const float* keyM  = (const float*)d_in[2];
    const float* mems  = (const float*)d_in[3];
    const void*  ids   = d_in[4];
    float* out = (float*)d_out;

    const int N = in_sizes[1] / D_DIM;

    cudaFuncSetAttribute(fused_kernel,
                         cudaFuncAttributeMaxDynamicSharedMemorySize, SMEM_TOTAL);

    fused_kernel<<<GRID, 256, SMEM_TOTAL>>>(items, users, keyM, mems, ids, out, N);
}